// round 9
// baseline (speedup 1.0000x reference)
#include <cuda_runtime.h>
#include <cstdint>
#include <cstddef>

#define B_ROWS 8192
#define KDIM   4096
#define KW     128              // 4096 bits / 32
#define NMAX   4096
#define RCHUNK 32
#define ROWS_PER_CHUNK (B_ROWS / RCHUNK)   // 256

#define TILE       128
#define SROW       132                      // padded row stride (words): 132 % 32 == 4
#define SMEM_GEMM  (2 * TILE * SROW * 4)    // 135168 bytes

// ---------------- scratch (device globals; no runtime allocation) ----------------
__device__ unsigned   g_A0[(size_t)B_ROWS * KW];        // 4 MB  packed activations ping
__device__ unsigned   g_A1[(size_t)B_ROWS * KW];        // 4 MB  packed activations pong
__device__ unsigned   g_Wb[(size_t)NMAX * KW];          // 2 MB  packed weights (per layer)
__device__ short      g_S [(size_t)B_ROWS * NMAX];      // 67 MB pre-BN int16 activations
__device__ int        g_psum  [RCHUNK * NMAX];
__device__ long long  g_psumsq[RCHUNK * NMAX];
__device__ int        g_pmax  [RCHUNK * NMAX];
__device__ int        g_pmin  [RCHUNK * NMAX];
__device__ float      g_mu[NMAX];
__device__ float      g_scale[NMAX];
__device__ float      g_amax[NMAX];
__device__ float      g_pexp[RCHUNK * 1024];
__device__ float      g_dinv[1024];

// ---------------- 1) binarize+pack x ----------------
__global__ void pack_x_kernel(const float* __restrict__ x) {
    unsigned idx = blockIdx.x * 256u + threadIdx.x;          // over B*K (exact)
    float v = x[idx];
    unsigned m = __ballot_sync(0xFFFFFFFFu, (v - 0.5f) >= 0.0f);
    if ((threadIdx.x & 31u) == 0u) g_A0[idx >> 5] = m;
}

// ---------------- 2) binarize+pack W, column-major bits: g_Wb[j][w] ----------------
__global__ void pack_w_kernel(const float* __restrict__ W, int N) {
    int j = blockIdx.x * 256 + threadIdx.x;                  // output column
    int w = blockIdx.y;                                      // k-word 0..127
    const float* p = W + (size_t)w * 32 * N + j;
    unsigned m = 0;
    #pragma unroll
    for (int b = 0; b < 32; ++b)
        if (p[(size_t)b * N] >= 0.0f) m |= (1u << b);
    g_Wb[(size_t)j * KW + w] = m;
}

// ---------------- 3) XNOR-popcount GEMM, [row][word] smem, LDS.128 fragments ----------------
__global__ __launch_bounds__(256, 1)
void gemm_popc_kernel(int which_a, int N) {
    const unsigned* __restrict__ A = which_a ? g_A1 : g_A0;
    extern __shared__ unsigned sm[];
    unsigned* sA = sm;                       // [128 rows][132 words]
    unsigned* sB = sm + TILE * SROW;

    int tid = threadIdx.x, wid = tid >> 5, lane = tid & 31;
    int tx = tid & 15, ty = tid >> 4;
    int rowBlk = blockIdx.y * TILE, colBlk = blockIdx.x * TILE;

    // one-shot coalesced load: warp w copies rows {p*8+w}, lane covers 16B chunks
    #pragma unroll
    for (int p = 0; p < 16; ++p) {
        int row = p * 8 + wid;
        uint4 va = *(const uint4*)(A    + (size_t)(rowBlk + row) * KW + lane * 4);
        uint4 vb = *(const uint4*)(g_Wb + (size_t)(colBlk + row) * KW + lane * 4);
        *(uint4*)&sA[row * SROW + lane * 4] = va;
        *(uint4*)&sB[row * SROW + lane * 4] = vb;
    }
    __syncthreads();

    int acc[8][8];
    #pragma unroll
    for (int m = 0; m < 8; ++m)
        #pragma unroll
        for (int n = 0; n < 8; ++n) acc[m][n] = 0;

    #pragma unroll 1
    for (int g = 0; g < KW / 4; ++g) {                       // 32 groups of 4 words
        int w0 = g * 4;
        uint4 a[8];
        #pragma unroll
        for (int mt = 0; mt < 8; ++mt)
            a[mt] = *(const uint4*)&sA[(ty + 16 * mt) * SROW + w0];
        #pragma unroll
        for (int nt = 0; nt < 8; ++nt) {
            uint4 b = *(const uint4*)&sB[(tx + 16 * nt) * SROW + w0];
            #pragma unroll
            for (int mt = 0; mt < 8; ++mt) {
                int p0 = __popc(a[mt].x ^ b.x);
                int p1 = __popc(a[mt].y ^ b.y);
                int p2 = __popc(a[mt].z ^ b.z);
                int p3 = __popc(a[mt].w ^ b.w);
                acc[mt][nt] += (p0 + p1) + (p2 + p3);
            }
        }
    }

    #pragma unroll
    for (int mt = 0; mt < 8; ++mt) {
        int row = rowBlk + ty + 16 * mt;
        #pragma unroll
        for (int nt = 0; nt < 8; ++nt) {
            int col = colBlk + tx + 16 * nt;
            g_S[(size_t)row * N + col] = (short)(KDIM - 2 * acc[mt][nt]);
        }
    }
}

// ---------------- 4) per-column partial stats (int16 source) ----------------
__global__ void colstats_kernel(int N) {
    int j = blockIdx.x * 256 + threadIdx.x;
    int c = blockIdx.y;
    const short* p = g_S + (size_t)c * ROWS_PER_CHUNK * N + j;
    int sum = 0;
    long long ss = 0;
    int mx = -2147483647, mn = 2147483647;
    #pragma unroll 8
    for (int r = 0; r < ROWS_PER_CHUNK; ++r) {
        int v = p[(size_t)r * N];
        sum += v; ss += v * v;
        mx = max(mx, v); mn = min(mn, v);
    }
    g_psum[c * N + j] = sum; g_psumsq[c * N + j] = ss;
    g_pmax[c * N + j] = mx;  g_pmin[c * N + j] = mn;
}

// ---------------- 5) finalize mu/scale/amax ----------------
__global__ void finalize_stats_kernel(const float* __restrict__ gamma,
                                      const float* __restrict__ beta,
                                      int layer, int N) {
    int j = blockIdx.x * 256 + threadIdx.x;
    long long sum = 0, ss = 0;
    int mx = -2147483647, mn = 2147483647;
    #pragma unroll
    for (int c = 0; c < RCHUNK; ++c) {
        sum += g_psum[c * N + j]; ss += g_psumsq[c * N + j];
        mx = max(mx, g_pmax[c * N + j]); mn = min(mn, g_pmin[c * N + j]);
    }
    double m   = (double)sum / (double)B_ROWS;
    double var = (double)ss  / (double)B_ROWS - m * m;
    float sc = gamma[layer] * rsqrtf((float)var + 1e-5f);
    float be = beta[layer];
    g_mu[j] = (float)m; g_scale[j] = sc;
    float hi = ((float)mx - (float)m) * sc + be;
    float lo = ((float)mn - (float)m) * sc + be;
    g_amax[j] = fmaxf(hi, lo);
}

// ---------------- 6) BN + binarize + repack ----------------
__global__ void bn_bin_pack_kernel(const float* __restrict__ beta,
                                   int layer, int which_out, int N) {
    unsigned idx = blockIdx.x * 256u + threadIdx.x;          // over B*N (exact)
    int j = idx & (unsigned)(N - 1);
    float a = ((float)g_S[idx] - g_mu[j]) * g_scale[j] + beta[layer];
    unsigned m = __ballot_sync(0xFFFFFFFFu, a >= 0.0f);
    unsigned* out = which_out ? g_A1 : g_A0;
    if ((threadIdx.x & 31u) == 0u) out[idx >> 5] = m;
}

// ---------------- 7) softmax over batch ----------------
__global__ void sumexp_kernel(const float* __restrict__ beta, int N) {
    int j = blockIdx.x * 256 + threadIdx.x;
    int c = blockIdx.y;
    float m = g_mu[j], sc = g_scale[j], be = beta[2], ax = g_amax[j];
    const short* p = g_S + (size_t)c * ROWS_PER_CHUNK * N + j;
    float sum = 0.0f;
    #pragma unroll 8
    for (int r = 0; r < ROWS_PER_CHUNK; ++r)
        sum += __expf(((float)p[(size_t)r * N] - m) * sc + be - ax);
    g_pexp[c * N + j] = sum;
}
__global__ void finalize_denom_kernel(int N) {
    int j = blockIdx.x * 256 + threadIdx.x;
    float s = 0.0f;
    #pragma unroll
    for (int c = 0; c < RCHUNK; ++c) s += g_pexp[c * N + j];
    g_dinv[j] = 1.0f / s;
}
__global__ void write_out_kernel(const float* __restrict__ beta,
                                 float* __restrict__ out, int N) {
    unsigned idx = blockIdx.x * 256u + threadIdx.x;
    int j = idx & (unsigned)(N - 1);
    float a = ((float)g_S[idx] - g_mu[j]) * g_scale[j] + beta[2] - g_amax[j];
    out[idx] = __expf(a) * g_dinv[j];
}

// ---------------- driver ----------------
extern "C" void kernel_launch(void* const* d_in, const int* in_sizes, int n_in,
                              void* d_out, int out_size) {
    (void)in_sizes; (void)n_in; (void)out_size;
    const float* x     = (const float*)d_in[0];
    const float* Ws[3] = {(const float*)d_in[1], (const float*)d_in[2], (const float*)d_in[3]};
    const float* gamma = (const float*)d_in[4];
    const float* beta  = (const float*)d_in[5];
    float* out = (float*)d_out;
    const int Ns[3] = {4096, 4096, 1024};

    cudaFuncSetAttribute(gemm_popc_kernel, cudaFuncAttributeMaxDynamicSharedMemorySize, SMEM_GEMM);

    pack_x_kernel<<<(B_ROWS * KDIM) / 256, 256>>>(x);

    int cur = 0;
    for (int k = 0; k < 3; ++k) {
        int N = Ns[k];
        pack_w_kernel<<<dim3(N / 256, KW), 256>>>(Ws[k], N);
        gemm_popc_kernel<<<dim3(N / TILE, B_ROWS / TILE), 256, SMEM_GEMM>>>(cur, N);
        colstats_kernel<<<dim3(N / 256, RCHUNK), 256>>>(N);
        finalize_stats_kernel<<<N / 256, 256>>>(gamma, beta, k, N);
        if (k < 2) {
            bn_bin_pack_kernel<<<(B_ROWS * N) / 256, 256>>>(beta, k, cur ^ 1, N);
            cur ^= 1;
        } else {
            sumexp_kernel<<<dim3(N / 256, RCHUNK), 256>>>(beta, N);
            finalize_denom_kernel<<<N / 256, 256>>>(N);
            write_out_kernel<<<(B_ROWS * N) / 256, 256>>>(beta, out, N);
        }
    }
}

// round 10
// speedup vs baseline: 1.3552x; 1.3552x over previous
#include <cuda_runtime.h>
#include <cstdint>
#include <cstddef>

#define B_ROWS 8192
#define KDIM   4096
#define KW     128              // 4096 bits / 32
#define NMAX   4096
#define RCHUNK 32
#define ROWS_PER_CHUNK (B_ROWS / RCHUNK)   // 256

#define TILE       128
#define SROW       129                      // padded row stride (words) in smem
#define SMEM_GEMM  (2 * TILE * SROW * 4)    // 132096 bytes

#define NCSA       15                       // 15 CSA groups of 7 words = 105
#define PLAIN0     (NCSA * 7)               // plain words 105..127 (23 words)

// ---------------- scratch (device globals; no runtime allocation) ----------------
__device__ unsigned   g_A0[(size_t)B_ROWS * KW];        // 4 MB  packed activations ping
__device__ unsigned   g_A1[(size_t)B_ROWS * KW];        // 4 MB  packed activations pong
__device__ unsigned   g_Wb[(size_t)NMAX * KW];          // 2 MB  packed weights (per layer)
__device__ short      g_S [(size_t)B_ROWS * NMAX];      // 67 MB pre-BN int16 activations
__device__ int        g_psum  [RCHUNK * NMAX];
__device__ long long  g_psumsq[RCHUNK * NMAX];
__device__ int        g_pmax  [RCHUNK * NMAX];
__device__ int        g_pmin  [RCHUNK * NMAX];
__device__ float      g_mu[NMAX];
__device__ float      g_scale[NMAX];
__device__ float      g_amax[NMAX];
__device__ float      g_pexp[RCHUNK * 1024];
__device__ float      g_dinv[1024];

template<int IMM>
__device__ __forceinline__ unsigned lop3(unsigned a, unsigned b, unsigned c) {
    unsigned r;
    asm("lop3.b32 %0, %1, %2, %3, %4;" : "=r"(r) : "r"(a), "r"(b), "r"(c), "n"(IMM));
    return r;
}

// ---------------- 1) binarize+pack x ----------------
__global__ void pack_x_kernel(const float* __restrict__ x) {
    unsigned idx = blockIdx.x * 256u + threadIdx.x;          // over B*K (exact)
    float v = x[idx];
    unsigned m = __ballot_sync(0xFFFFFFFFu, (v - 0.5f) >= 0.0f);
    if ((threadIdx.x & 31u) == 0u) g_A0[idx >> 5] = m;
}

// ---------------- 2) binarize+pack W, column-major bits: g_Wb[j][w] ----------------
__global__ void pack_w_kernel(const float* __restrict__ W, int N) {
    int j = blockIdx.x * 256 + threadIdx.x;                  // output column
    int w = blockIdx.y;                                      // k-word 0..127
    const float* p = W + (size_t)w * 32 * N + j;
    unsigned m = 0;
    #pragma unroll
    for (int b = 0; b < 32; ++b)
        if (p[(size_t)b * N] >= 0.0f) m |= (1u << b);
    g_Wb[(size_t)j * KW + w] = m;
}

// ---------------- 3) XNOR GEMM: 15 x 7:3-CSA groups + 23 plain-popcount words ----------------
// smem layout [word][row] (row stride 129 words); thread rows strided by 16 -> conflict-free LDS.
__global__ __launch_bounds__(256, 1)
void gemm_popc_kernel(int which_a, int N) {
    const unsigned* __restrict__ A = which_a ? g_A1 : g_A0;
    extern __shared__ unsigned sm[];
    unsigned* sA = sm;
    unsigned* sB = sm + TILE * SROW;

    int tid = threadIdx.x, wid = tid >> 5, lane = tid & 31;
    int tx = tid & 15, ty = tid >> 4;
    int rowBlk = blockIdx.y * TILE, colBlk = blockIdx.x * TILE;

    // one-shot load + transpose into [word][row]
    #pragma unroll
    for (int p = 0; p < 16; ++p) {
        int row = p * 8 + wid;
        uint4 va = *(const uint4*)(A    + (size_t)(rowBlk + row) * KW + lane * 4);
        uint4 vb = *(const uint4*)(g_Wb + (size_t)(colBlk + row) * KW + lane * 4);
        sA[(lane * 4 + 0) * SROW + row] = va.x;
        sA[(lane * 4 + 1) * SROW + row] = va.y;
        sA[(lane * 4 + 2) * SROW + row] = va.z;
        sA[(lane * 4 + 3) * SROW + row] = va.w;
        sB[(lane * 4 + 0) * SROW + row] = vb.x;
        sB[(lane * 4 + 1) * SROW + row] = vb.y;
        sB[(lane * 4 + 2) * SROW + row] = vb.z;
        sB[(lane * 4 + 3) * SROW + row] = vb.w;
    }
    __syncthreads();

    int acc[8][8];                                            // weighted mismatch counts
    #pragma unroll
    for (int m = 0; m < 8; ++m)
        #pragma unroll
        for (int n = 0; n < 8; ++n) acc[m][n] = 0;

    // ---- CSA part: 15 groups of 7 words ----
    unsigned aF[8][7];
    for (int g = 0; g < NCSA; ++g) {
        int w0 = g * 7;
        #pragma unroll
        for (int mt = 0; mt < 8; ++mt)
            #pragma unroll
            for (int i = 0; i < 7; ++i)
                aF[mt][i] = sA[(w0 + i) * SROW + ty + 16 * mt];
        #pragma unroll
        for (int nt = 0; nt < 8; ++nt) {
            unsigned b[7];
            #pragma unroll
            for (int i = 0; i < 7; ++i)
                b[i] = sB[(w0 + i) * SROW + tx + 16 * nt];
            #pragma unroll
            for (int mt = 0; mt < 8; ++mt) {
                unsigned x0 = aF[mt][0] ^ b[0], x1 = aF[mt][1] ^ b[1];
                unsigned x2 = aF[mt][2] ^ b[2], x3 = aF[mt][3] ^ b[3];
                unsigned x4 = aF[mt][4] ^ b[4], x5 = aF[mt][5] ^ b[5];
                unsigned x6 = aF[mt][6] ^ b[6];
                unsigned s0 = lop3<0x96>(x0, x1, x2), c0 = lop3<0xE8>(x0, x1, x2);
                unsigned s1 = lop3<0x96>(x3, x4, x5), c1 = lop3<0xE8>(x3, x4, x5);
                unsigned s2 = lop3<0x96>(s0, s1, x6), c2 = lop3<0xE8>(s0, s1, x6);
                unsigned s3 = lop3<0x96>(c0, c1, c2), c3 = lop3<0xE8>(c0, c1, c2);
                acc[mt][nt] += __popc(s2) + 2 * __popc(s3) + 4 * __popc(c3);
            }
        }
    }

    // ---- plain part: words 105..127 (11 pairs + 1 single), popc-pipe fill ----
    for (int w0 = PLAIN0; w0 + 1 < KW; w0 += 2) {
        unsigned aP[8][2];
        #pragma unroll
        for (int mt = 0; mt < 8; ++mt) {
            aP[mt][0] = sA[(w0 + 0) * SROW + ty + 16 * mt];
            aP[mt][1] = sA[(w0 + 1) * SROW + ty + 16 * mt];
        }
        #pragma unroll
        for (int nt = 0; nt < 8; ++nt) {
            unsigned b0 = sB[(w0 + 0) * SROW + tx + 16 * nt];
            unsigned b1 = sB[(w0 + 1) * SROW + tx + 16 * nt];
            #pragma unroll
            for (int mt = 0; mt < 8; ++mt)
                acc[mt][nt] += __popc(aP[mt][0] ^ b0) + __popc(aP[mt][1] ^ b1);
        }
    }
    {   // last word (127)
        unsigned aL[8];
        #pragma unroll
        for (int mt = 0; mt < 8; ++mt)
            aL[mt] = sA[127 * SROW + ty + 16 * mt];
        #pragma unroll
        for (int nt = 0; nt < 8; ++nt) {
            unsigned b0 = sB[127 * SROW + tx + 16 * nt];
            #pragma unroll
            for (int mt = 0; mt < 8; ++mt)
                acc[mt][nt] += __popc(aL[mt] ^ b0);
        }
    }

    #pragma unroll
    for (int mt = 0; mt < 8; ++mt) {
        int row = rowBlk + ty + 16 * mt;
        #pragma unroll
        for (int nt = 0; nt < 8; ++nt) {
            int col = colBlk + tx + 16 * nt;
            g_S[(size_t)row * N + col] = (short)(KDIM - 2 * acc[mt][nt]);
        }
    }
}

// ---------------- 4) per-column partial stats (int16 source) ----------------
__global__ void colstats_kernel(int N) {
    int j = blockIdx.x * 256 + threadIdx.x;
    int c = blockIdx.y;
    const short* p = g_S + (size_t)c * ROWS_PER_CHUNK * N + j;
    int sum = 0;
    long long ss = 0;
    int mx = -2147483647, mn = 2147483647;
    #pragma unroll 8
    for (int r = 0; r < ROWS_PER_CHUNK; ++r) {
        int v = p[(size_t)r * N];
        sum += v; ss += v * v;
        mx = max(mx, v); mn = min(mn, v);
    }
    g_psum[c * N + j] = sum; g_psumsq[c * N + j] = ss;
    g_pmax[c * N + j] = mx;  g_pmin[c * N + j] = mn;
}

// ---------------- 5) finalize mu/scale/amax ----------------
__global__ void finalize_stats_kernel(const float* __restrict__ gamma,
                                      const float* __restrict__ beta,
                                      int layer, int N) {
    int j = blockIdx.x * 256 + threadIdx.x;
    long long sum = 0, ss = 0;
    int mx = -2147483647, mn = 2147483647;
    #pragma unroll
    for (int c = 0; c < RCHUNK; ++c) {
        sum += g_psum[c * N + j]; ss += g_psumsq[c * N + j];
        mx = max(mx, g_pmax[c * N + j]); mn = min(mn, g_pmin[c * N + j]);
    }
    double m   = (double)sum / (double)B_ROWS;
    double var = (double)ss  / (double)B_ROWS - m * m;
    float sc = gamma[layer] * rsqrtf((float)var + 1e-5f);
    float be = beta[layer];
    g_mu[j] = (float)m; g_scale[j] = sc;
    float hi = ((float)mx - (float)m) * sc + be;
    float lo = ((float)mn - (float)m) * sc + be;
    g_amax[j] = fmaxf(hi, lo);
}

// ---------------- 6) BN + binarize + repack ----------------
__global__ void bn_bin_pack_kernel(const float* __restrict__ beta,
                                   int layer, int which_out, int N) {
    unsigned idx = blockIdx.x * 256u + threadIdx.x;          // over B*N (exact)
    int j = idx & (unsigned)(N - 1);
    float a = ((float)g_S[idx] - g_mu[j]) * g_scale[j] + beta[layer];
    unsigned m = __ballot_sync(0xFFFFFFFFu, a >= 0.0f);
    unsigned* out = which_out ? g_A1 : g_A0;
    if ((threadIdx.x & 31u) == 0u) out[idx >> 5] = m;
}

// ---------------- 7) softmax over batch ----------------
__global__ void sumexp_kernel(const float* __restrict__ beta, int N) {
    int j = blockIdx.x * 256 + threadIdx.x;
    int c = blockIdx.y;
    float m = g_mu[j], sc = g_scale[j], be = beta[2], ax = g_amax[j];
    const short* p = g_S + (size_t)c * ROWS_PER_CHUNK * N + j;
    float sum = 0.0f;
    #pragma unroll 8
    for (int r = 0; r < ROWS_PER_CHUNK; ++r)
        sum += __expf(((float)p[(size_t)r * N] - m) * sc + be - ax);
    g_pexp[c * N + j] = sum;
}
__global__ void finalize_denom_kernel(int N) {
    int j = blockIdx.x * 256 + threadIdx.x;
    float s = 0.0f;
    #pragma unroll
    for (int c = 0; c < RCHUNK; ++c) s += g_pexp[c * N + j];
    g_dinv[j] = 1.0f / s;
}
__global__ void write_out_kernel(const float* __restrict__ beta,
                                 float* __restrict__ out, int N) {
    unsigned idx = blockIdx.x * 256u + threadIdx.x;
    int j = idx & (unsigned)(N - 1);
    float a = ((float)g_S[idx] - g_mu[j]) * g_scale[j] + beta[2] - g_amax[j];
    out[idx] = __expf(a) * g_dinv[j];
}

// ---------------- driver ----------------
extern "C" void kernel_launch(void* const* d_in, const int* in_sizes, int n_in,
                              void* d_out, int out_size) {
    (void)in_sizes; (void)n_in; (void)out_size;
    const float* x     = (const float*)d_in[0];
    const float* Ws[3] = {(const float*)d_in[1], (const float*)d_in[2], (const float*)d_in[3]};
    const float* gamma = (const float*)d_in[4];
    const float* beta  = (const float*)d_in[5];
    float* out = (float*)d_out;
    const int Ns[3] = {4096, 4096, 1024};

    cudaFuncSetAttribute(gemm_popc_kernel, cudaFuncAttributeMaxDynamicSharedMemorySize, SMEM_GEMM);

    pack_x_kernel<<<(B_ROWS * KDIM) / 256, 256>>>(x);

    int cur = 0;
    for (int k = 0; k < 3; ++k) {
        int N = Ns[k];
        pack_w_kernel<<<dim3(N / 256, KW), 256>>>(Ws[k], N);
        gemm_popc_kernel<<<dim3(N / TILE, B_ROWS / TILE), 256, SMEM_GEMM>>>(cur, N);
        colstats_kernel<<<dim3(N / 256, RCHUNK), 256>>>(N);
        finalize_stats_kernel<<<N / 256, 256>>>(gamma, beta, k, N);
        if (k < 2) {
            bn_bin_pack_kernel<<<(B_ROWS * N) / 256, 256>>>(beta, k, cur ^ 1, N);
            cur ^= 1;
        } else {
            sumexp_kernel<<<dim3(N / 256, RCHUNK), 256>>>(beta, N);
            finalize_denom_kernel<<<N / 256, 256>>>(N);
            write_out_kernel<<<(B_ROWS * N) / 256, 256>>>(beta, out, N);
        }
    }
}

// round 11
// speedup vs baseline: 1.3814x; 1.0193x over previous
#include <cuda_runtime.h>
#include <cstdint>
#include <cstddef>

#define B_ROWS 8192
#define KDIM   4096
#define KW     128              // 4096 bits / 32
#define NMAX   4096
#define RCHUNK 32
#define ROWS_PER_CHUNK (B_ROWS / RCHUNK)   // 256

#define TILE       128
#define SROW       129                      // padded row stride (words) in smem
#define SMEM_GEMM  (2 * TILE * SROW * 4)    // 132096 bytes

#define NCSA       16                       // 16 CSA groups of 7 words = 112
#define PLAIN0     (NCSA * 7)               // plain words 112..127 (8 pairs)

// ---------------- scratch (device globals; no runtime allocation) ----------------
__device__ unsigned   g_A0[(size_t)B_ROWS * KW];        // 4 MB  packed activations ping
__device__ unsigned   g_A1[(size_t)B_ROWS * KW];        // 4 MB  packed activations pong
__device__ unsigned   g_Wb[(size_t)NMAX * KW];          // 2 MB  packed weights (per layer)
__device__ short      g_S [(size_t)B_ROWS * NMAX];      // 67 MB pre-BN int16 activations
__device__ int        g_psum  [RCHUNK * NMAX];
__device__ long long  g_psumsq[RCHUNK * NMAX];
__device__ int        g_pmax  [RCHUNK * NMAX];
__device__ int        g_pmin  [RCHUNK * NMAX];
__device__ float      g_mu[NMAX];
__device__ float      g_scale[NMAX];
__device__ float      g_amax[NMAX];
__device__ float      g_pexp[RCHUNK * 1024];
__device__ float      g_dinv[1024];

template<int IMM>
__device__ __forceinline__ unsigned lop3(unsigned a, unsigned b, unsigned c) {
    unsigned r;
    asm("lop3.b32 %0, %1, %2, %3, %4;" : "=r"(r) : "r"(a), "r"(b), "r"(c), "n"(IMM));
    return r;
}

// ---------------- 1) binarize+pack x ----------------
__global__ void pack_x_kernel(const float* __restrict__ x) {
    unsigned idx = blockIdx.x * 256u + threadIdx.x;          // over B*K (exact)
    float v = x[idx];
    unsigned m = __ballot_sync(0xFFFFFFFFu, (v - 0.5f) >= 0.0f);
    if ((threadIdx.x & 31u) == 0u) g_A0[idx >> 5] = m;
}

// ---------------- 2) binarize+pack W, column-major bits: g_Wb[j][w] ----------------
__global__ void pack_w_kernel(const float* __restrict__ W, int N) {
    int j = blockIdx.x * 256 + threadIdx.x;                  // output column
    int w = blockIdx.y;                                      // k-word 0..127
    const float* p = W + (size_t)w * 32 * N + j;
    unsigned m = 0;
    #pragma unroll
    for (int b = 0; b < 32; ++b)
        if (p[(size_t)b * N] >= 0.0f) m |= (1u << b);
    g_Wb[(size_t)j * KW + w] = m;
}

// ---------------- 3) XNOR GEMM: 16 x 7:3-CSA groups + 8 plain pairs, 512 thr ----------------
// smem layout [word][row] (row stride 129 words).
// 512 threads: ty = tid>>4 (0..31) -> rows ty+32*mt (mt<4); tx = tid&15 -> cols tx+16*nt (nt<8)
__global__ __launch_bounds__(512, 1)
void gemm_popc_kernel(int which_a, int N) {
    const unsigned* __restrict__ A = which_a ? g_A1 : g_A0;
    extern __shared__ unsigned sm[];
    unsigned* sA = sm;
    unsigned* sB = sm + TILE * SROW;

    int tid = threadIdx.x, wid = tid >> 5, lane = tid & 31;
    int tx = tid & 15, ty = tid >> 4;
    int rowBlk = blockIdx.y * TILE, colBlk = blockIdx.x * TILE;

    // one-shot load + transpose into [word][row]: warp w copies rows {p*16+w}
    #pragma unroll
    for (int p = 0; p < 8; ++p) {
        int row = p * 16 + wid;
        uint4 va = *(const uint4*)(A    + (size_t)(rowBlk + row) * KW + lane * 4);
        uint4 vb = *(const uint4*)(g_Wb + (size_t)(colBlk + row) * KW + lane * 4);
        sA[(lane * 4 + 0) * SROW + row] = va.x;
        sA[(lane * 4 + 1) * SROW + row] = va.y;
        sA[(lane * 4 + 2) * SROW + row] = va.z;
        sA[(lane * 4 + 3) * SROW + row] = va.w;
        sB[(lane * 4 + 0) * SROW + row] = vb.x;
        sB[(lane * 4 + 1) * SROW + row] = vb.y;
        sB[(lane * 4 + 2) * SROW + row] = vb.z;
        sB[(lane * 4 + 3) * SROW + row] = vb.w;
    }
    __syncthreads();

    int acc[4][8];                                            // weighted mismatch counts
    #pragma unroll
    for (int m = 0; m < 4; ++m)
        #pragma unroll
        for (int n = 0; n < 8; ++n) acc[m][n] = 0;

    // ---- CSA part: 16 groups of 7 words (words 0..111) ----
    unsigned aF[4][7];
    for (int g = 0; g < NCSA; ++g) {
        int w0 = g * 7;
        #pragma unroll
        for (int mt = 0; mt < 4; ++mt)
            #pragma unroll
            for (int i = 0; i < 7; ++i)
                aF[mt][i] = sA[(w0 + i) * SROW + ty + 32 * mt];
        #pragma unroll
        for (int nt = 0; nt < 8; ++nt) {
            unsigned b[7];
            #pragma unroll
            for (int i = 0; i < 7; ++i)
                b[i] = sB[(w0 + i) * SROW + tx + 16 * nt];
            #pragma unroll
            for (int mt = 0; mt < 4; ++mt) {
                unsigned x0 = aF[mt][0] ^ b[0], x1 = aF[mt][1] ^ b[1];
                unsigned x2 = aF[mt][2] ^ b[2], x3 = aF[mt][3] ^ b[3];
                unsigned x4 = aF[mt][4] ^ b[4], x5 = aF[mt][5] ^ b[5];
                unsigned x6 = aF[mt][6] ^ b[6];
                unsigned s0 = lop3<0x96>(x0, x1, x2), c0 = lop3<0xE8>(x0, x1, x2);
                unsigned s1 = lop3<0x96>(x3, x4, x5), c1 = lop3<0xE8>(x3, x4, x5);
                unsigned s2 = lop3<0x96>(s0, s1, x6), c2 = lop3<0xE8>(s0, s1, x6);
                unsigned s3 = lop3<0x96>(c0, c1, c2), c3 = lop3<0xE8>(c0, c1, c2);
                acc[mt][nt] += __popc(s2) + 2 * __popc(s3) + 4 * __popc(c3);
            }
        }
    }

    // ---- plain part: words 112..127 as 8 pairs (popc-pipe fill) ----
    #pragma unroll
    for (int pr = 0; pr < 8; ++pr) {
        int w0 = PLAIN0 + pr * 2;
        unsigned aP[4][2];
        #pragma unroll
        for (int mt = 0; mt < 4; ++mt) {
            aP[mt][0] = sA[(w0 + 0) * SROW + ty + 32 * mt];
            aP[mt][1] = sA[(w0 + 1) * SROW + ty + 32 * mt];
        }
        #pragma unroll
        for (int nt = 0; nt < 8; ++nt) {
            unsigned b0 = sB[(w0 + 0) * SROW + tx + 16 * nt];
            unsigned b1 = sB[(w0 + 1) * SROW + tx + 16 * nt];
            #pragma unroll
            for (int mt = 0; mt < 4; ++mt)
                acc[mt][nt] += __popc(aP[mt][0] ^ b0) + __popc(aP[mt][1] ^ b1);
        }
    }

    #pragma unroll
    for (int mt = 0; mt < 4; ++mt) {
        int row = rowBlk + ty + 32 * mt;
        #pragma unroll
        for (int nt = 0; nt < 8; ++nt) {
            int col = colBlk + tx + 16 * nt;
            g_S[(size_t)row * N + col] = (short)(KDIM - 2 * acc[mt][nt]);
        }
    }
}

// ---------------- 4) per-column partial stats (int16 source) ----------------
__global__ void colstats_kernel(int N) {
    int j = blockIdx.x * 256 + threadIdx.x;
    int c = blockIdx.y;
    const short* p = g_S + (size_t)c * ROWS_PER_CHUNK * N + j;
    int sum = 0;
    long long ss = 0;
    int mx = -2147483647, mn = 2147483647;
    #pragma unroll 8
    for (int r = 0; r < ROWS_PER_CHUNK; ++r) {
        int v = p[(size_t)r * N];
        sum += v; ss += v * v;
        mx = max(mx, v); mn = min(mn, v);
    }
    g_psum[c * N + j] = sum; g_psumsq[c * N + j] = ss;
    g_pmax[c * N + j] = mx;  g_pmin[c * N + j] = mn;
}

// ---------------- 5) finalize mu/scale/amax ----------------
__global__ void finalize_stats_kernel(const float* __restrict__ gamma,
                                      const float* __restrict__ beta,
                                      int layer, int N) {
    int j = blockIdx.x * 256 + threadIdx.x;
    long long sum = 0, ss = 0;
    int mx = -2147483647, mn = 2147483647;
    #pragma unroll
    for (int c = 0; c < RCHUNK; ++c) {
        sum += g_psum[c * N + j]; ss += g_psumsq[c * N + j];
        mx = max(mx, g_pmax[c * N + j]); mn = min(mn, g_pmin[c * N + j]);
    }
    double m   = (double)sum / (double)B_ROWS;
    double var = (double)ss  / (double)B_ROWS - m * m;
    float sc = gamma[layer] * rsqrtf((float)var + 1e-5f);
    float be = beta[layer];
    g_mu[j] = (float)m; g_scale[j] = sc;
    float hi = ((float)mx - (float)m) * sc + be;
    float lo = ((float)mn - (float)m) * sc + be;
    g_amax[j] = fmaxf(hi, lo);
}

// ---------------- 6) BN + binarize + repack ----------------
__global__ void bn_bin_pack_kernel(const float* __restrict__ beta,
                                   int layer, int which_out, int N) {
    unsigned idx = blockIdx.x * 256u + threadIdx.x;          // over B*N (exact)
    int j = idx & (unsigned)(N - 1);
    float a = ((float)g_S[idx] - g_mu[j]) * g_scale[j] + beta[layer];
    unsigned m = __ballot_sync(0xFFFFFFFFu, a >= 0.0f);
    unsigned* out = which_out ? g_A1 : g_A0;
    if ((threadIdx.x & 31u) == 0u) out[idx >> 5] = m;
}

// ---------------- 7) softmax over batch ----------------
__global__ void sumexp_kernel(const float* __restrict__ beta, int N) {
    int j = blockIdx.x * 256 + threadIdx.x;
    int c = blockIdx.y;
    float m = g_mu[j], sc = g_scale[j], be = beta[2], ax = g_amax[j];
    const short* p = g_S + (size_t)c * ROWS_PER_CHUNK * N + j;
    float sum = 0.0f;
    #pragma unroll 8
    for (int r = 0; r < ROWS_PER_CHUNK; ++r)
        sum += __expf(((float)p[(size_t)r * N] - m) * sc + be - ax);
    g_pexp[c * N + j] = sum;
}
__global__ void finalize_denom_kernel(int N) {
    int j = blockIdx.x * 256 + threadIdx.x;
    float s = 0.0f;
    #pragma unroll
    for (int c = 0; c < RCHUNK; ++c) s += g_pexp[c * N + j];
    g_dinv[j] = 1.0f / s;
}
__global__ void write_out_kernel(const float* __restrict__ beta,
                                 float* __restrict__ out, int N) {
    unsigned idx = blockIdx.x * 256u + threadIdx.x;
    int j = idx & (unsigned)(N - 1);
    float a = ((float)g_S[idx] - g_mu[j]) * g_scale[j] + beta[2] - g_amax[j];
    out[idx] = __expf(a) * g_dinv[j];
}

// ---------------- driver ----------------
extern "C" void kernel_launch(void* const* d_in, const int* in_sizes, int n_in,
                              void* d_out, int out_size) {
    (void)in_sizes; (void)n_in; (void)out_size;
    const float* x     = (const float*)d_in[0];
    const float* Ws[3] = {(const float*)d_in[1], (const float*)d_in[2], (const float*)d_in[3]};
    const float* gamma = (const float*)d_in[4];
    const float* beta  = (const float*)d_in[5];
    float* out = (float*)d_out;
    const int Ns[3] = {4096, 4096, 1024};

    cudaFuncSetAttribute(gemm_popc_kernel, cudaFuncAttributeMaxDynamicSharedMemorySize, SMEM_GEMM);

    pack_x_kernel<<<(B_ROWS * KDIM) / 256, 256>>>(x);

    int cur = 0;
    for (int k = 0; k < 3; ++k) {
        int N = Ns[k];
        pack_w_kernel<<<dim3(N / 256, KW), 256>>>(Ws[k], N);
        gemm_popc_kernel<<<dim3(N / TILE, B_ROWS / TILE), 512, SMEM_GEMM>>>(cur, N);
        colstats_kernel<<<dim3(N / 256, RCHUNK), 256>>>(N);
        finalize_stats_kernel<<<N / 256, 256>>>(gamma, beta, k, N);
        if (k < 2) {
            bn_bin_pack_kernel<<<(B_ROWS * N) / 256, 256>>>(beta, k, cur ^ 1, N);
            cur ^= 1;
        } else {
            sumexp_kernel<<<dim3(N / 256, RCHUNK), 256>>>(beta, N);
            finalize_denom_kernel<<<N / 256, 256>>>(N);
            write_out_kernel<<<(B_ROWS * N) / 256, 256>>>(beta, out, N);
        }
    }
}

// round 12
// speedup vs baseline: 1.4577x; 1.0552x over previous
#include <cuda_runtime.h>
#include <cstdint>
#include <cstddef>

#define B_ROWS 8192
#define KDIM   4096
#define KW     128              // 4096 bits / 32
#define NMAX   4096
#define RCHUNK 32
#define ROWS_PER_CHUNK (B_ROWS / RCHUNK)   // 256

#define TILE       128
#define SROW       129                      // padded row stride (words) in smem
#define SMEM_GEMM  (2 * TILE * SROW * 4)    // 132096 bytes

// ---------------- scratch (device globals; no runtime allocation) ----------------
__device__ unsigned   g_A0[(size_t)B_ROWS * KW];        // 4 MB  packed activations ping
__device__ unsigned   g_A1[(size_t)B_ROWS * KW];        // 4 MB  packed activations pong
__device__ unsigned   g_Wb[(size_t)NMAX * KW];          // 2 MB  packed weights (per layer)
__device__ short      g_S [(size_t)B_ROWS * NMAX];      // 67 MB pre-BN int16 activations
__device__ int        g_psum  [RCHUNK * NMAX];
__device__ long long  g_psumsq[RCHUNK * NMAX];
__device__ int        g_pmax  [RCHUNK * NMAX];
__device__ int        g_pmin  [RCHUNK * NMAX];
__device__ float      g_mu[NMAX];
__device__ float      g_scale[NMAX];
__device__ float      g_amax[NMAX];
__device__ float      g_pexp[RCHUNK * 1024];
__device__ float      g_dinv[1024];

template<int IMM>
__device__ __forceinline__ unsigned lop3(unsigned a, unsigned b, unsigned c) {
    unsigned r;
    asm("lop3.b32 %0, %1, %2, %3, %4;" : "=r"(r) : "r"(a), "r"(b), "r"(c), "n"(IMM));
    return r;
}

// ---------------- 1) binarize+pack x ----------------
__global__ void pack_x_kernel(const float* __restrict__ x) {
    unsigned idx = blockIdx.x * 256u + threadIdx.x;          // over B*K (exact)
    float v = x[idx];
    unsigned m = __ballot_sync(0xFFFFFFFFu, (v - 0.5f) >= 0.0f);
    if ((threadIdx.x & 31u) == 0u) g_A0[idx >> 5] = m;
}

// ---------------- 2) binarize+pack W, column-major bits: g_Wb[j][w] ----------------
__global__ void pack_w_kernel(const float* __restrict__ W, int N) {
    int j = blockIdx.x * 256 + threadIdx.x;                  // output column
    int w = blockIdx.y;                                      // k-word 0..127
    const float* p = W + (size_t)w * 32 * N + j;
    unsigned m = 0;
    #pragma unroll
    for (int b = 0; b < 32; ++b)
        if (p[(size_t)b * N] >= 0.0f) m |= (1u << b);
    g_Wb[(size_t)j * KW + w] = m;
}

// ---------------- 3) XNOR GEMM (R8 structure): 18 x 7:3-CSA groups + 2 plain words ----------------
// smem layout [word][row] (row stride 129 words); thread rows strided by 16 -> conflict-free LDS.
__global__ __launch_bounds__(256, 1)
void gemm_popc_kernel(int which_a, int N) {
    const unsigned* __restrict__ A = which_a ? g_A1 : g_A0;
    extern __shared__ unsigned sm[];
    unsigned* sA = sm;
    unsigned* sB = sm + TILE * SROW;

    int tid = threadIdx.x, wid = tid >> 5, lane = tid & 31;
    int tx = tid & 15, ty = tid >> 4;
    int rowBlk = blockIdx.y * TILE, colBlk = blockIdx.x * TILE;

    // one-shot load + transpose into [word][row]
    #pragma unroll
    for (int p = 0; p < 16; ++p) {
        int row = p * 8 + wid;
        uint4 va = *(const uint4*)(A    + (size_t)(rowBlk + row) * KW + lane * 4);
        uint4 vb = *(const uint4*)(g_Wb + (size_t)(colBlk + row) * KW + lane * 4);
        sA[(lane * 4 + 0) * SROW + row] = va.x;
        sA[(lane * 4 + 1) * SROW + row] = va.y;
        sA[(lane * 4 + 2) * SROW + row] = va.z;
        sA[(lane * 4 + 3) * SROW + row] = va.w;
        sB[(lane * 4 + 0) * SROW + row] = vb.x;
        sB[(lane * 4 + 1) * SROW + row] = vb.y;
        sB[(lane * 4 + 2) * SROW + row] = vb.z;
        sB[(lane * 4 + 3) * SROW + row] = vb.w;
    }
    __syncthreads();

    int acc[8][8];                                            // weighted mismatch counts
    #pragma unroll
    for (int m = 0; m < 8; ++m)
        #pragma unroll
        for (int n = 0; n < 8; ++n) acc[m][n] = 0;

    unsigned aF[8][7];
    for (int g = 0; g < 18; ++g) {                            // 18 groups of 7 words
        int w0 = g * 7;
        #pragma unroll
        for (int mt = 0; mt < 8; ++mt)
            #pragma unroll
            for (int i = 0; i < 7; ++i)
                aF[mt][i] = sA[(w0 + i) * SROW + ty + 16 * mt];
        #pragma unroll
        for (int nt = 0; nt < 8; ++nt) {
            unsigned b[7];
            #pragma unroll
            for (int i = 0; i < 7; ++i)
                b[i] = sB[(w0 + i) * SROW + tx + 16 * nt];
            #pragma unroll
            for (int mt = 0; mt < 8; ++mt) {
                unsigned x0 = aF[mt][0] ^ b[0], x1 = aF[mt][1] ^ b[1];
                unsigned x2 = aF[mt][2] ^ b[2], x3 = aF[mt][3] ^ b[3];
                unsigned x4 = aF[mt][4] ^ b[4], x5 = aF[mt][5] ^ b[5];
                unsigned x6 = aF[mt][6] ^ b[6];
                unsigned s0 = lop3<0x96>(x0, x1, x2), c0 = lop3<0xE8>(x0, x1, x2);
                unsigned s1 = lop3<0x96>(x3, x4, x5), c1 = lop3<0xE8>(x3, x4, x5);
                unsigned s2 = lop3<0x96>(s0, s1, x6), c2 = lop3<0xE8>(s0, s1, x6);
                unsigned s3 = lop3<0x96>(c0, c1, c2), c3 = lop3<0xE8>(c0, c1, c2);
                acc[mt][nt] += __popc(s2) + 2 * __popc(s3) + 4 * __popc(c3);
            }
        }
    }
    // leftover words 126, 127 (weight-1 direct popcounts)
    {
        unsigned aL[8][2];
        #pragma unroll
        for (int mt = 0; mt < 8; ++mt) {
            aL[mt][0] = sA[126 * SROW + ty + 16 * mt];
            aL[mt][1] = sA[127 * SROW + ty + 16 * mt];
        }
        #pragma unroll
        for (int nt = 0; nt < 8; ++nt) {
            unsigned b0 = sB[126 * SROW + tx + 16 * nt];
            unsigned b1 = sB[127 * SROW + tx + 16 * nt];
            #pragma unroll
            for (int mt = 0; mt < 8; ++mt)
                acc[mt][nt] += __popc(aL[mt][0] ^ b0) + __popc(aL[mt][1] ^ b1);
        }
    }

    #pragma unroll
    for (int mt = 0; mt < 8; ++mt) {
        int row = rowBlk + ty + 16 * mt;
        #pragma unroll
        for (int nt = 0; nt < 8; ++nt) {
            int col = colBlk + tx + 16 * nt;
            g_S[(size_t)row * N + col] = (short)(KDIM - 2 * acc[mt][nt]);
        }
    }
}

// ---------------- 4) per-column partial stats (short2: 2 cols/thread) ----------------
__global__ void colstats_kernel(int N) {
    int j2 = blockIdx.x * 256 + threadIdx.x;                 // pair index
    int j = j2 * 2;
    int c = blockIdx.y;
    const short* p = g_S + (size_t)c * ROWS_PER_CHUNK * N + j;
    int sum0 = 0, sum1 = 0;
    long long ss0 = 0, ss1 = 0;
    int mx0 = -2147483647, mn0 = 2147483647;
    int mx1 = -2147483647, mn1 = 2147483647;
    #pragma unroll 8
    for (int r = 0; r < ROWS_PER_CHUNK; ++r) {
        short2 v = *(const short2*)(p + (size_t)r * N);
        int v0 = v.x, v1 = v.y;
        sum0 += v0; ss0 += v0 * v0; mx0 = max(mx0, v0); mn0 = min(mn0, v0);
        sum1 += v1; ss1 += v1 * v1; mx1 = max(mx1, v1); mn1 = min(mn1, v1);
    }
    g_psum[c * N + j]   = sum0; g_psumsq[c * N + j]   = ss0;
    g_pmax[c * N + j]   = mx0;  g_pmin[c * N + j]   = mn0;
    g_psum[c * N + j+1] = sum1; g_psumsq[c * N + j+1] = ss1;
    g_pmax[c * N + j+1] = mx1;  g_pmin[c * N + j+1] = mn1;
}

// ---------------- 5) finalize mu/scale/amax ----------------
__global__ void finalize_stats_kernel(const float* __restrict__ gamma,
                                      const float* __restrict__ beta,
                                      int layer, int N) {
    int j = blockIdx.x * 256 + threadIdx.x;
    long long sum = 0, ss = 0;
    int mx = -2147483647, mn = 2147483647;
    #pragma unroll
    for (int c = 0; c < RCHUNK; ++c) {
        sum += g_psum[c * N + j]; ss += g_psumsq[c * N + j];
        mx = max(mx, g_pmax[c * N + j]); mn = min(mn, g_pmin[c * N + j]);
    }
    double m   = (double)sum / (double)B_ROWS;
    double var = (double)ss  / (double)B_ROWS - m * m;
    float sc = gamma[layer] * rsqrtf((float)var + 1e-5f);
    float be = beta[layer];
    g_mu[j] = (float)m; g_scale[j] = sc;
    float hi = ((float)mx - (float)m) * sc + be;
    float lo = ((float)mn - (float)m) * sc + be;
    g_amax[j] = fmaxf(hi, lo);
}

// ---------------- 6) BN + binarize + repack ----------------
__global__ void bn_bin_pack_kernel(const float* __restrict__ beta,
                                   int layer, int which_out, int N) {
    unsigned idx = blockIdx.x * 256u + threadIdx.x;          // over B*N (exact)
    int j = idx & (unsigned)(N - 1);
    float a = ((float)g_S[idx] - g_mu[j]) * g_scale[j] + beta[layer];
    unsigned m = __ballot_sync(0xFFFFFFFFu, a >= 0.0f);
    unsigned* out = which_out ? g_A1 : g_A0;
    if ((threadIdx.x & 31u) == 0u) out[idx >> 5] = m;
}

// ---------------- 7) softmax over batch ----------------
__global__ void sumexp_kernel(const float* __restrict__ beta, int N) {
    int j = blockIdx.x * 256 + threadIdx.x;
    int c = blockIdx.y;
    float m = g_mu[j], sc = g_scale[j], be = beta[2], ax = g_amax[j];
    const short* p = g_S + (size_t)c * ROWS_PER_CHUNK * N + j;
    float sum = 0.0f;
    #pragma unroll 8
    for (int r = 0; r < ROWS_PER_CHUNK; ++r)
        sum += __expf(((float)p[(size_t)r * N] - m) * sc + be - ax);
    g_pexp[c * N + j] = sum;
}
__global__ void finalize_denom_kernel(int N) {
    int j = blockIdx.x * 256 + threadIdx.x;
    float s = 0.0f;
    #pragma unroll
    for (int c = 0; c < RCHUNK; ++c) s += g_pexp[c * N + j];
    g_dinv[j] = 1.0f / s;
}
__global__ void write_out_kernel(const float* __restrict__ beta,
                                 float* __restrict__ out, int N) {
    unsigned idx = blockIdx.x * 256u + threadIdx.x;
    int j = idx & (unsigned)(N - 1);
    float a = ((float)g_S[idx] - g_mu[j]) * g_scale[j] + beta[2] - g_amax[j];
    out[idx] = __expf(a) * g_dinv[j];
}

// ---------------- driver ----------------
extern "C" void kernel_launch(void* const* d_in, const int* in_sizes, int n_in,
                              void* d_out, int out_size) {
    (void)in_sizes; (void)n_in; (void)out_size;
    const float* x     = (const float*)d_in[0];
    const float* Ws[3] = {(const float*)d_in[1], (const float*)d_in[2], (const float*)d_in[3]};
    const float* gamma = (const float*)d_in[4];
    const float* beta  = (const float*)d_in[5];
    float* out = (float*)d_out;
    const int Ns[3] = {4096, 4096, 1024};

    cudaFuncSetAttribute(gemm_popc_kernel, cudaFuncAttributeMaxDynamicSharedMemorySize, SMEM_GEMM);

    pack_x_kernel<<<(B_ROWS * KDIM) / 256, 256>>>(x);

    int cur = 0;
    for (int k = 0; k < 3; ++k) {
        int N = Ns[k];
        pack_w_kernel<<<dim3(N / 256, KW), 256>>>(Ws[k], N);
        gemm_popc_kernel<<<dim3(N / TILE, B_ROWS / TILE), 256, SMEM_GEMM>>>(cur, N);
        colstats_kernel<<<dim3(N / 512, RCHUNK), 256>>>(N);
        finalize_stats_kernel<<<N / 256, 256>>>(gamma, beta, k, N);
        if (k < 2) {
            bn_bin_pack_kernel<<<(B_ROWS * N) / 256, 256>>>(beta, k, cur ^ 1, N);
            cur ^= 1;
        } else {
            sumexp_kernel<<<dim3(N / 256, RCHUNK), 256>>>(beta, N);
            finalize_denom_kernel<<<N / 256, 256>>>(N);
            write_out_kernel<<<(B_ROWS * N) / 256, 256>>>(beta, out, N);
        }
    }
}